// round 6
// baseline (speedup 1.0000x reference)
#include <cuda_runtime.h>

// y[n,c,h,w] = a0*x[h] + a1*(x[h-1]+x[h+1]) + a2*(x[h-2]+x[h+2]) + a3*(x[h-3]+x[h+3])
// reflect indexing along H. x: (N, C, 256, 256) fp32, alpha: (C, 4) fp32.

#define HH 256
#define WW 256
#define W4 (WW / 4)      // 64 float4 per row
#define SEG 64           // output rows per work unit
#define SEGS (HH / SEG)  // 4 segments per plane
#define UNITS_PER_BLOCK 4

__device__ __forceinline__ int refl(int i) {
    i = (i < 0) ? -i : i;
    return (i < HH) ? i : (2 * HH - 2 - i);
}

__global__ __launch_bounds__(256, 2)
void hartley_conv_kernel(const float4* __restrict__ x,
                         const float*  __restrict__ alpha,
                         float4* __restrict__ y,
                         int nunits, int C)
{
    const int unit = blockIdx.x * UNITS_PER_BLOCK + (threadIdx.x >> 6);
    const int lane = threadIdx.x & 63;
    if (unit >= nunits) return;

    const int seg   = unit & (SEGS - 1);
    const int plane = unit >> 2;           // SEGS == 4
    const int c     = plane & (256 - 1);   // C == 256; fallback below if not
    const int cc    = (C == 256) ? c : (plane % C);

    const float a0 = __ldg(alpha + cc * 4 + 0);
    const float a1 = __ldg(alpha + cc * 4 + 1);
    const float a2 = __ldg(alpha + cc * 4 + 2);
    const float a3 = __ldg(alpha + cc * 4 + 3);

    const int h0 = seg * SEG;
    const float4* __restrict__ xp = x + (size_t)plane * (HH * W4) + lane;
    float4*       __restrict__ yp = y + ((size_t)plane * HH + h0) * W4 + lane;

    // Window invariant at top of iter i (h = h0+i): r0..r6 = rows h-3..h+3,
    // p0..p3 = rows h+4..h+7 (prefetched).
    float4 r0 = __ldcs(xp + refl(h0 - 3) * W4);
    float4 r1 = __ldcs(xp + refl(h0 - 2) * W4);
    float4 r2 = __ldcs(xp + refl(h0 - 1) * W4);
    float4 r3 = __ldcs(xp + (h0    ) * W4);
    float4 r4 = __ldcs(xp + (h0 + 1) * W4);
    float4 r5 = __ldcs(xp + (h0 + 2) * W4);
    float4 r6 = __ldcs(xp + (h0 + 3) * W4);
    float4 p0 = __ldcs(xp + refl(h0 + 4) * W4);
    float4 p1 = __ldcs(xp + refl(h0 + 5) * W4);
    float4 p2 = __ldcs(xp + refl(h0 + 6) * W4);
    float4 p3 = __ldcs(xp + refl(h0 + 7) * W4);

    #pragma unroll 8
    for (int i = 0; i < SEG; ++i) {
        float4 out;
        out.x = fmaf(a3, r0.x + r6.x, fmaf(a2, r1.x + r5.x, fmaf(a1, r2.x + r4.x, a0 * r3.x)));
        out.y = fmaf(a3, r0.y + r6.y, fmaf(a2, r1.y + r5.y, fmaf(a1, r2.y + r4.y, a0 * r3.y)));
        out.z = fmaf(a3, r0.z + r6.z, fmaf(a2, r1.z + r5.z, fmaf(a1, r2.z + r4.z, a0 * r3.z)));
        out.w = fmaf(a3, r0.w + r6.w, fmaf(a2, r1.w + r5.w, fmaf(a1, r2.w + r4.w, a0 * r3.w)));
        __stcs(yp + i * W4, out);

        // rotate window + prefetch pipe
        r0 = r1; r1 = r2; r2 = r3; r3 = r4; r4 = r5; r5 = r6;
        r6 = p0; p0 = p1; p1 = p2; p2 = p3;

        // load row h0+i+8; only consumed if loaded at i <= SEG-6 (used for
        // output row h0+i+5). Predicate off the dead tail loads.
        if (i < SEG - 5) {
            int nh = h0 + i + 8;
            if (nh >= HH) nh = 2 * HH - 2 - nh;
            p3 = __ldcs(xp + nh * W4);
        }
    }
}

extern "C" void kernel_launch(void* const* d_in, const int* in_sizes, int n_in,
                              void* d_out, int out_size)
{
    const float4* x     = (const float4*)d_in[0];
    const float*  alpha = (const float*)d_in[1];
    float4*       y     = (float4*)d_out;

    const int C      = in_sizes[1] / 4;          // alpha is (C, 4)
    const int planes = in_sizes[0] / (HH * WW);  // N * C
    const int nunits = planes * SEGS;

    const int grid = (nunits + UNITS_PER_BLOCK - 1) / UNITS_PER_BLOCK;
    hartley_conv_kernel<<<grid, 256>>>(x, alpha, y, nunits, C);
}

// round 7
// speedup vs baseline: 1.3488x; 1.3488x over previous
#include <cuda_runtime.h>

// y[h] = a0*x[h] + a1*(x[h-1]+x[h+1]) + a2*(x[h-2]+x[h+2]) + a3*(x[h-3]+x[h+3])
// reflect indexing along H. x: (N, C, 256, 256) fp32, alpha: (C, 4) fp32.

#define HH 256
#define WW 256
#define W4 (WW / 4)           // 64 float4 per row
#define PLANES_PER_BLOCK 4    // 4 * 64 = 256 threads

__device__ __forceinline__ int refl(int i) {
    i = (i < 0) ? -i : i;
    return (i < HH) ? i : (2 * HH - 2 - i);
}

__global__ __launch_bounds__(256, 2)
void hartley_conv_kernel(const float4* __restrict__ x,
                         const float*  __restrict__ alpha,
                         float4* __restrict__ y,
                         int planes, int C)
{
    const int plane = blockIdx.x * PLANES_PER_BLOCK + (threadIdx.x >> 6);
    const int lane  = threadIdx.x & 63;
    if (plane >= planes) return;

    const int c = plane % C;
    const float a0 = alpha[c * 4 + 0];
    const float a1 = alpha[c * 4 + 1];
    const float a2 = alpha[c * 4 + 2];
    const float a3 = alpha[c * 4 + 3];

    const float4* __restrict__ xp = x + (size_t)plane * (HH * W4) + lane;
    float4*       __restrict__ yp = y + (size_t)plane * (HH * W4) + lane;

    // Window: w0..w6 = rows -3..3 (reflected); n0..n3 = rows 4..7 (next batch).
    float4 w0, w1, w2, w3, w4, w5, w6, n0, n1, n2, n3;
    w3 = xp[0 * W4];
    w2 = xp[1 * W4]; w4 = w2;
    w1 = xp[2 * W4]; w5 = w1;
    w0 = xp[3 * W4]; w6 = w0;
    n0 = xp[4 * W4];
    n1 = xp[5 * W4];
    n2 = xp[6 * W4];
    n3 = xp[7 * W4];

#define TAP(o, p0, p1, p2, p3_, p4, p5, p6)                                             \
    o.x = fmaf(a3, p0.x + p6.x, fmaf(a2, p1.x + p5.x, fmaf(a1, p2.x + p4.x, a0 * p3_.x))); \
    o.y = fmaf(a3, p0.y + p6.y, fmaf(a2, p1.y + p5.y, fmaf(a1, p2.y + p4.y, a0 * p3_.y))); \
    o.z = fmaf(a3, p0.z + p6.z, fmaf(a2, p1.z + p5.z, fmaf(a1, p2.z + p4.z, a0 * p3_.z))); \
    o.w = fmaf(a3, p0.w + p6.w, fmaf(a2, p1.w + p5.w, fmaf(a1, p2.w + p4.w, a0 * p3_.w)))

    #pragma unroll 1
    for (int i = 0; i < HH; i += 4) {
        // Issue next batch (rows i+8..i+11, reflected near the end) FIRST —
        // 4 independent unconditional loads in flight during the compute below.
        // They are consumed one full iteration later.
        float4 m0 = xp[refl(i +  8) * W4];
        float4 m1 = xp[refl(i +  9) * W4];
        float4 m2 = xp[refl(i + 10) * W4];
        float4 m3 = xp[refl(i + 11) * W4];

        // Outputs for rows i..i+3 use only data loaded >= 1 iteration ago.
        float4 o0, o1, o2, o3;
        TAP(o0, w0, w1, w2, w3, w4, w5, w6);
        TAP(o1, w1, w2, w3, w4, w5, w6, n0);
        TAP(o2, w2, w3, w4, w5, w6, n0, n1);
        TAP(o3, w3, w4, w5, w6, n0, n1, n2);
        yp[(i + 0) * W4] = o0;
        yp[(i + 1) * W4] = o1;
        yp[(i + 2) * W4] = o2;
        yp[(i + 3) * W4] = o3;

        // Shift window by 4 rows.
        w0 = w4; w1 = w5; w2 = w6;
        w3 = n0; w4 = n1; w5 = n2; w6 = n3;
        n0 = m0; n1 = m1; n2 = m2; n3 = m3;
    }
#undef TAP
}

extern "C" void kernel_launch(void* const* d_in, const int* in_sizes, int n_in,
                              void* d_out, int out_size)
{
    const float4* x     = (const float4*)d_in[0];
    const float*  alpha = (const float*)d_in[1];
    float4*       y     = (float4*)d_out;

    const int C      = in_sizes[1] / 4;          // alpha is (C, 4)
    const int planes = in_sizes[0] / (HH * WW);  // N * C

    const int grid = (planes + PLANES_PER_BLOCK - 1) / PLANES_PER_BLOCK;
    hartley_conv_kernel<<<grid, 256>>>(x, alpha, y, planes, C);
}